// round 2
// baseline (speedup 1.0000x reference)
#include <cuda_runtime.h>
#include <math.h>

#define N_NODES 116
#define N_EDGES 1160
#define C_IN    64
#define T_IN    657
#define C_OUT   256
#define F_DIM   653
#define LDF     656               // padded row stride (mult of 4 -> float4 aligned)
#define M_ROWS  (N_NODES * C_OUT) // 29696
#define NPAD    768               // padded N for weight tiles (6 * 128)
#define KTILES  82                // 656 / 8

// ---------------- device scratch (static; no allocation at runtime) -------------
__device__ float g_bufA[(size_t)M_ROWS * LDF];
__device__ float g_bufB[(size_t)M_ROWS * LDF];
__device__ float g_agg [(size_t)M_ROWS * LDF];
__device__ float g_wl  [(size_t)NPAD * LDF];
__device__ float g_wr  [(size_t)NPAD * LDF];
__device__ int   g_offs[N_NODES + 1];
__device__ int   g_list[N_EDGES];
__device__ float g_mean[C_OUT * LDF];
__device__ float g_fc1 [C_OUT * 128];

// ---------------- CSR build (single block) --------------------------------------
// edge_index is int32 on device (JAX x64-disabled downcasts the int64 request).
__global__ void build_csr(const int* __restrict__ ei) {
    __shared__ int cnt[N_NODES + 1];
    __shared__ int offs[N_NODES + 1];
    int tid = threadIdx.x;
    for (int i = tid; i <= N_NODES; i += blockDim.x) cnt[i] = 0;
    __syncthreads();
    for (int e = tid; e < N_EDGES; e += blockDim.x) {
        int dst = min(max(ei[N_EDGES + e], 0), N_NODES - 1);
        atomicAdd(&cnt[dst], 1);
    }
    __syncthreads();
    if (tid == 0) {
        int s = 0;
        for (int i = 0; i < N_NODES; i++) { offs[i] = s; s += cnt[i]; }
        offs[N_NODES] = s;
    }
    __syncthreads();
    for (int i = tid; i <= N_NODES; i += blockDim.x) {
        g_offs[i] = offs[i];
        cnt[i] = offs[i];   // reuse as cursor
    }
    __syncthreads();
    for (int e = tid; e < N_EDGES; e += blockDim.x) {
        int src = min(max(ei[e], 0), N_NODES - 1);
        int dst = min(max(ei[N_EDGES + e], 0), N_NODES - 1);
        int pos = atomicAdd(&cnt[dst], 1);
        if (pos >= 0 && pos < N_EDGES) g_list[pos] = src;
    }
}

// ---------------- weight padding: [653,653] -> [768,656] zero-padded ------------
__global__ void pad_weights(const float* __restrict__ wl, const float* __restrict__ wr) {
    int idx = blockIdx.x * blockDim.x + threadIdx.x;
    if (idx >= NPAD * LDF) return;
    int r = idx / LDF, c = idx % LDF;
    float vl = 0.f, vr = 0.f;
    if (r < F_DIM && c < F_DIM) {
        vl = wl[(size_t)r * F_DIM + c];
        vr = wr[(size_t)r * F_DIM + c];
    }
    g_wl[idx] = vl;
    g_wr[idx] = vr;
}

// ---------------- grouped Conv1d: [116,64,657] -> bufA [29696, LDF] --------------
// block = (node n, group g); 16 in-ch * 657 samples in smem + 64*80 weights in smem
#define XS_STRIDE 660
#define CONV_SMEM ((16 * XS_STRIDE + 64 * 80) * 4)
__global__ void conv1d_grouped(const float* __restrict__ x,
                               const float* __restrict__ w,
                               const float* __restrict__ b) {
    extern __shared__ float smem[];
    float* xs = smem;                  // [16][XS_STRIDE]
    float* ws = smem + 16 * XS_STRIDE; // [64][80]
    int n = blockIdx.x, g = blockIdx.y;
    int tid = threadIdx.x;

    const float* xbase = x + ((size_t)n * C_IN + (size_t)g * 16) * T_IN;
    for (int i = tid; i < 16 * T_IN; i += blockDim.x) {
        int ic = i / T_IN, t = i % T_IN;
        xs[ic * XS_STRIDE + t] = xbase[i];
    }
    for (int i = tid; i < 64 * 80; i += blockDim.x)
        ws[i] = w[(size_t)g * 64 * 80 + i];
    __syncthreads();

    // each task = one out channel (local) x 4 consecutive t values; 164 t-tiles
    for (int task = tid; task < 64 * 164; task += blockDim.x) {
        int oc = task / 164;
        int t0 = (task % 164) * 4;
        float bias = b[g * 64 + oc];
        float a0 = bias, a1 = bias, a2 = bias, a3 = bias;
        const float* wrow = &ws[oc * 80];
#pragma unroll
        for (int i = 0; i < 16; i++) {
            float4 x0 = *(const float4*)&xs[i * XS_STRIDE + t0];
            float4 x1 = *(const float4*)&xs[i * XS_STRIDE + t0 + 4];
            float xv[8] = {x0.x, x0.y, x0.z, x0.w, x1.x, x1.y, x1.z, x1.w};
#pragma unroll
            for (int k = 0; k < 5; k++) {
                float wv = wrow[i * 5 + k];
                a0 = fmaf(xv[0 + k], wv, a0);
                a1 = fmaf(xv[1 + k], wv, a1);
                a2 = fmaf(xv[2 + k], wv, a2);
                a3 = fmaf(xv[3 + k], wv, a3);
            }
        }
        float* out = &g_bufA[((size_t)n * C_OUT + g * 64 + oc) * LDF + t0];
        out[0] = (t0 + 0 < F_DIM) ? a0 : 0.f;
        out[1] = (t0 + 1 < F_DIM) ? a1 : 0.f;
        out[2] = (t0 + 2 < F_DIM) ? a2 : 0.f;
        out[3] = (t0 + 3 < F_DIM) ? a3 : 0.f;
    }
}

// ---------------- SAGE max-aggregation: agg[n,c,:] = max over in-edges -----------
__global__ void sage_agg(int src) {
    const float* h = src ? g_bufB : g_bufA;
    int row = blockIdx.x;            // = n*256 + c
    int n = row >> 8;
    int c = row & 255;
    int beg = g_offs[n], end = g_offs[n + 1];
    float4* out = (float4*)(g_agg + (size_t)row * LDF);
    for (int v = threadIdx.x; v < LDF / 4; v += blockDim.x) {
        float4 m = make_float4(0.f, 0.f, 0.f, 0.f);
        if (end > beg) {
            m = make_float4(-3.4e38f, -3.4e38f, -3.4e38f, -3.4e38f);
            for (int e = beg; e < end; e++) {
                int s = g_list[e];
                float4 t = *(const float4*)(h + ((size_t)s * C_OUT + c) * LDF + v * 4);
                m.x = fmaxf(m.x, t.x); m.y = fmaxf(m.y, t.y);
                m.z = fmaxf(m.z, t.z); m.w = fmaxf(m.w, t.w);
            }
        }
        out[v] = m;
    }
}

// ---------------- fused SAGE GEMM: out = agg@Wl^T + h@Wr^T + b -------------------
// NT gemm, both operands K-contiguous with LDF stride. BM=BN=128, BK=8, 8x8/thread.
// K loop runs 164 tiles: phase 0 = (agg, Wl), phase 1 = (h, Wr). Double-buffered.
__global__ void __launch_bounds__(256, 2) sage_gemm(int src, const float* __restrict__ bias) {
    __shared__ float As[2][8][128];
    __shared__ float Bs[2][8][128];
    const float* H   = src ? g_bufB : g_bufA;
    float*       Out = src ? g_bufA : g_bufB;
    const float* Ap[2] = {g_agg, H};
    const float* Bp[2] = {g_wl, g_wr};

    const int tid = threadIdx.x;
    const int m0 = blockIdx.x * 128;
    const int n0 = blockIdx.y * 128;
    const int lr = tid >> 1;          // row within tile for loads
    const int lc = (tid & 1) * 4;     // k offset for loads
    const int tx = tid & 15;
    const int ty = tid >> 4;

    float acc[8][8];
#pragma unroll
    for (int i = 0; i < 8; i++)
#pragma unroll
        for (int j = 0; j < 8; j++) acc[i][j] = 0.f;

    // prologue: load first tile (phase 0, k0 = 0)
    {
        float4 a4 = *(const float4*)(Ap[0] + (size_t)(m0 + lr) * LDF + lc);
        float4 b4 = *(const float4*)(Bp[0] + (size_t)(n0 + lr) * LDF + lc);
        As[0][lc + 0][lr] = a4.x; As[0][lc + 1][lr] = a4.y;
        As[0][lc + 2][lr] = a4.z; As[0][lc + 3][lr] = a4.w;
        Bs[0][lc + 0][lr] = b4.x; Bs[0][lc + 1][lr] = b4.y;
        Bs[0][lc + 2][lr] = b4.z; Bs[0][lc + 3][lr] = b4.w;
    }
    __syncthreads();

    const int STEPS = 2 * KTILES;  // 164
    int buf = 0;
    for (int s = 0; s < STEPS; s++) {
        int ns = s + 1;
        bool hasNext = ns < STEPS;
        float4 na, nb;
        if (hasNext) {
            int ph = (ns >= KTILES) ? 1 : 0;
            int k0 = (ns - ph * KTILES) * 8;
            na = *(const float4*)(Ap[ph] + (size_t)(m0 + lr) * LDF + k0 + lc);
            nb = *(const float4*)(Bp[ph] + (size_t)(n0 + lr) * LDF + k0 + lc);
        }
#pragma unroll
        for (int k = 0; k < 8; k++) {
            float4 a0 = *(const float4*)&As[buf][k][ty * 8];
            float4 a1 = *(const float4*)&As[buf][k][ty * 8 + 4];
            float4 b0 = *(const float4*)&Bs[buf][k][tx * 8];
            float4 b1 = *(const float4*)&Bs[buf][k][tx * 8 + 4];
            float ar[8] = {a0.x, a0.y, a0.z, a0.w, a1.x, a1.y, a1.z, a1.w};
            float br[8] = {b0.x, b0.y, b0.z, b0.w, b1.x, b1.y, b1.z, b1.w};
#pragma unroll
            for (int i = 0; i < 8; i++)
#pragma unroll
                for (int j = 0; j < 8; j++)
                    acc[i][j] = fmaf(ar[i], br[j], acc[i][j]);
        }
        if (hasNext) {
            int nbuf = buf ^ 1;
            As[nbuf][lc + 0][lr] = na.x; As[nbuf][lc + 1][lr] = na.y;
            As[nbuf][lc + 2][lr] = na.z; As[nbuf][lc + 3][lr] = na.w;
            Bs[nbuf][lc + 0][lr] = nb.x; Bs[nbuf][lc + 1][lr] = nb.y;
            Bs[nbuf][lc + 2][lr] = nb.z; Bs[nbuf][lc + 3][lr] = nb.w;
        }
        __syncthreads();
        buf ^= 1;
    }

    // epilogue: add bias, write (zero the padded tail columns so next layer is clean)
#pragma unroll
    for (int i = 0; i < 8; i++) {
        int row = m0 + ty * 8 + i;
        float* orow = Out + (size_t)row * LDF;
#pragma unroll
        for (int j = 0; j < 8; j++) {
            int col = n0 + tx * 8 + j;
            if (col < F_DIM)      orow[col] = acc[i][j] + bias[col];
            else if (col < LDF)   orow[col] = 0.f;
        }
    }
}

// ---------------- mean pool over nodes: [116,256,LDF] -> g_mean [256,LDF] --------
__global__ void mean_pool(int src) {
    const float* h = src ? g_bufB : g_bufA;
    int idx = blockIdx.x * blockDim.x + threadIdx.x;
    if (idx >= C_OUT * LDF) return;
    int c = idx / LDF, f = idx % LDF;
    float s = 0.f;
    for (int n = 0; n < N_NODES; n++)
        s += h[((size_t)n * C_OUT + c) * LDF + f];
    g_mean[idx] = s * (1.f / N_NODES);
}

__device__ __forceinline__ float gelu_exact(float x) {
    return 0.5f * x * (1.f + erff(x * 0.70710678118654752f));
}

// ---------------- fc1 + gelu: [256,653] x [128,653]^T -> g_fc1 [256,128] ---------
__global__ void fc1_kernel(const float* __restrict__ w, const float* __restrict__ b) {
    __shared__ float row[F_DIM];
    int c = blockIdx.x;
    int tid = threadIdx.x;
    for (int f = tid; f < F_DIM; f += blockDim.x) row[f] = g_mean[c * LDF + f];
    __syncthreads();
    int warp = tid >> 5, lane = tid & 31;
    for (int g = warp; g < 128; g += blockDim.x / 32) {
        const float* wr = w + (size_t)g * F_DIM;
        float acc = 0.f;
        for (int f = lane; f < F_DIM; f += 32) acc = fmaf(row[f], wr[f], acc);
#pragma unroll
        for (int o = 16; o; o >>= 1) acc += __shfl_xor_sync(0xffffffffu, acc, o);
        if (lane == 0) g_fc1[c * 128 + g] = gelu_exact(acc + b[g]);
    }
}

// ---------------- fc2 + gelu + fc3 + softmax: -> out [256,4] ---------------------
__global__ void head_kernel(const float* __restrict__ f2w, const float* __restrict__ f2b,
                            const float* __restrict__ f3w, const float* __restrict__ f3b,
                            float* __restrict__ out) {
    __shared__ float r1[128];
    __shared__ float r2[32];
    __shared__ float r3[4];
    int c = blockIdx.x;
    int tid = threadIdx.x;  // 32 threads
    for (int i = tid; i < 128; i += 32) r1[i] = g_fc1[c * 128 + i];
    __syncthreads();
    {
        float acc = f2b[tid];
        const float* wr = f2w + (size_t)tid * 128;
        for (int f = 0; f < 128; f++) acc = fmaf(r1[f], wr[f], acc);
        r2[tid] = gelu_exact(acc);
    }
    __syncthreads();
    if (tid < 4) {
        float a = f3b[tid];
        const float* wr = f3w + (size_t)tid * 32;
        for (int f = 0; f < 32; f++) a = fmaf(r2[f], wr[f], a);
        r3[tid] = a;
    }
    __syncthreads();
    if (tid == 0) {
        float mx = fmaxf(fmaxf(r3[0], r3[1]), fmaxf(r3[2], r3[3]));
        float e0 = expf(r3[0] - mx), e1 = expf(r3[1] - mx);
        float e2 = expf(r3[2] - mx), e3 = expf(r3[3] - mx);
        float inv = 1.f / (e0 + e1 + e2 + e3);
        out[c * 4 + 0] = e0 * inv;
        out[c * 4 + 1] = e1 * inv;
        out[c * 4 + 2] = e2 * inv;
        out[c * 4 + 3] = e3 * inv;
    }
}

// ---------------- launch ---------------------------------------------------------
extern "C" void kernel_launch(void* const* d_in, const int* in_sizes, int n_in,
                              void* d_out, int out_size) {
    const float* x      = (const float*)d_in[0];
    const int*   ei     = (const int*)d_in[1];
    const float* conv_w = (const float*)d_in[2];
    const float* conv_b = (const float*)d_in[3];
    const float* wl     = (const float*)d_in[4];
    const float* wr     = (const float*)d_in[5];
    const float* sb     = (const float*)d_in[6];
    const float* f1w    = (const float*)d_in[7];
    const float* f1b    = (const float*)d_in[8];
    const float* f2w    = (const float*)d_in[9];
    const float* f2b    = (const float*)d_in[10];
    const float* f3w    = (const float*)d_in[11];
    const float* f3b    = (const float*)d_in[12];
    float* out = (float*)d_out;

    cudaFuncSetAttribute(conv1d_grouped,
                         cudaFuncAttributeMaxDynamicSharedMemorySize, CONV_SMEM);

    build_csr<<<1, 128>>>(ei);
    pad_weights<<<(NPAD * LDF + 255) / 256, 256>>>(wl, wr);
    conv1d_grouped<<<dim3(N_NODES, 4), 256, CONV_SMEM>>>(x, conv_w, conv_b);

    // 3 SAGE layers, ping-pong A<->B.  layer0: A->B, layer1: B->A, layer2: A->B
    for (int l = 0; l < 3; l++) {
        int src = l & 1;
        sage_agg<<<M_ROWS, 128>>>(src);
        sage_gemm<<<dim3(M_ROWS / 128, NPAD / 128), 256>>>(src, sb);
    }

    mean_pool<<<(C_OUT * LDF + 255) / 256, 256>>>(1 /* final result lives in bufB */);
    fc1_kernel<<<256, 128>>>(f1w, f1b);
    head_kernel<<<256, 32>>>(f2w, f2b, f3w, f3b, out);
}

// round 3
// speedup vs baseline: 1.0041x; 1.0041x over previous
#include <cuda_runtime.h>
#include <math.h>

#define N_NODES 116
#define N_EDGES 1160
#define C_IN    64
#define T_IN    657
#define C_OUT   256
#define F_DIM   653
#define LDF     656               // padded row stride (mult of 4 -> float4 aligned)
#define M_ROWS  (N_NODES * C_OUT) // 29696
#define NPAD    768               // padded N for weight tiles (6 * 128)
#define KTILES  82                // 656 / 8

// ---------------- device scratch (static; no allocation at runtime) -------------
__device__ float g_bufA[(size_t)M_ROWS * LDF];
__device__ float g_bufB[(size_t)M_ROWS * LDF];
__device__ float g_agg [(size_t)M_ROWS * LDF];
__device__ float g_wl  [(size_t)NPAD * LDF];
__device__ float g_wr  [(size_t)NPAD * LDF];
__device__ int   g_offs[N_NODES + 1];
__device__ int   g_list[N_EDGES];
__device__ float g_mean[C_OUT * LDF];
__device__ float g_fc1 [C_OUT * 128];

// ---------------- CSR build (single block) --------------------------------------
// edge_index is int32 on device (JAX x64-disabled downcasts the int64 request).
__global__ void build_csr(const int* __restrict__ ei) {
    __shared__ int cnt[N_NODES + 1];
    __shared__ int offs[N_NODES + 1];
    int tid = threadIdx.x;
    for (int i = tid; i <= N_NODES; i += blockDim.x) cnt[i] = 0;
    __syncthreads();
    for (int e = tid; e < N_EDGES; e += blockDim.x) {
        int dst = min(max(ei[N_EDGES + e], 0), N_NODES - 1);
        atomicAdd(&cnt[dst], 1);
    }
    __syncthreads();
    if (tid == 0) {
        int s = 0;
        for (int i = 0; i < N_NODES; i++) { offs[i] = s; s += cnt[i]; }
        offs[N_NODES] = s;
    }
    __syncthreads();
    for (int i = tid; i <= N_NODES; i += blockDim.x) {
        g_offs[i] = offs[i];
        cnt[i] = offs[i];   // reuse as cursor
    }
    __syncthreads();
    for (int e = tid; e < N_EDGES; e += blockDim.x) {
        int src = min(max(ei[e], 0), N_NODES - 1);
        int dst = min(max(ei[N_EDGES + e], 0), N_NODES - 1);
        int pos = atomicAdd(&cnt[dst], 1);
        if (pos >= 0 && pos < N_EDGES) g_list[pos] = src;
    }
}

// ---------------- weight padding: [653,653] -> [768,656] zero-padded ------------
__global__ void pad_weights(const float* __restrict__ wl, const float* __restrict__ wr) {
    int idx = blockIdx.x * blockDim.x + threadIdx.x;
    if (idx >= NPAD * LDF) return;
    int r = idx / LDF, c = idx % LDF;
    float vl = 0.f, vr = 0.f;
    if (r < F_DIM && c < F_DIM) {
        vl = wl[(size_t)r * F_DIM + c];
        vr = wr[(size_t)r * F_DIM + c];
    }
    g_wl[idx] = vl;
    g_wr[idx] = vr;
}

// ---------------- grouped Conv1d: [116,64,657] -> bufA [29696, LDF] --------------
// block = (node n, group g); 16 in-ch * 657 samples in smem + 64*80 weights in smem
#define XS_STRIDE 660
#define CONV_SMEM ((16 * XS_STRIDE + 64 * 80) * 4)
__global__ void conv1d_grouped(const float* __restrict__ x,
                               const float* __restrict__ w,
                               const float* __restrict__ b) {
    extern __shared__ float smem[];
    float* xs = smem;                  // [16][XS_STRIDE]
    float* ws = smem + 16 * XS_STRIDE; // [64][80]
    int n = blockIdx.x, g = blockIdx.y;
    int tid = threadIdx.x;

    const float* xbase = x + ((size_t)n * C_IN + (size_t)g * 16) * T_IN;
    for (int i = tid; i < 16 * T_IN; i += blockDim.x) {
        int ic = i / T_IN, t = i % T_IN;
        xs[ic * XS_STRIDE + t] = xbase[i];
    }
    for (int i = tid; i < 64 * 80; i += blockDim.x)
        ws[i] = w[(size_t)g * 64 * 80 + i];
    __syncthreads();

    // each task = one out channel (local) x 4 consecutive t values; 164 t-tiles
    for (int task = tid; task < 64 * 164; task += blockDim.x) {
        int oc = task / 164;
        int t0 = (task % 164) * 4;
        float bias = b[g * 64 + oc];
        float a0 = bias, a1 = bias, a2 = bias, a3 = bias;
        const float* wrow = &ws[oc * 80];
#pragma unroll
        for (int i = 0; i < 16; i++) {
            float4 x0 = *(const float4*)&xs[i * XS_STRIDE + t0];
            float4 x1 = *(const float4*)&xs[i * XS_STRIDE + t0 + 4];
            float xv[8] = {x0.x, x0.y, x0.z, x0.w, x1.x, x1.y, x1.z, x1.w};
#pragma unroll
            for (int k = 0; k < 5; k++) {
                float wv = wrow[i * 5 + k];
                a0 = fmaf(xv[0 + k], wv, a0);
                a1 = fmaf(xv[1 + k], wv, a1);
                a2 = fmaf(xv[2 + k], wv, a2);
                a3 = fmaf(xv[3 + k], wv, a3);
            }
        }
        float* out = &g_bufA[((size_t)n * C_OUT + g * 64 + oc) * LDF + t0];
        out[0] = (t0 + 0 < F_DIM) ? a0 : 0.f;
        out[1] = (t0 + 1 < F_DIM) ? a1 : 0.f;
        out[2] = (t0 + 2 < F_DIM) ? a2 : 0.f;
        out[3] = (t0 + 3 < F_DIM) ? a3 : 0.f;
    }
}

// ---------------- SAGE max-aggregation: agg[n,c,:] = max over in-edges -----------
__global__ void sage_agg(int src) {
    const float* h = src ? g_bufB : g_bufA;
    int row = blockIdx.x;            // = n*256 + c
    int n = row >> 8;
    int c = row & 255;
    int beg = g_offs[n], end = g_offs[n + 1];
    float4* out = (float4*)(g_agg + (size_t)row * LDF);
    for (int v = threadIdx.x; v < LDF / 4; v += blockDim.x) {
        float4 m = make_float4(0.f, 0.f, 0.f, 0.f);
        if (end > beg) {
            m = make_float4(-3.4e38f, -3.4e38f, -3.4e38f, -3.4e38f);
            for (int e = beg; e < end; e++) {
                int s = g_list[e];
                float4 t = *(const float4*)(h + ((size_t)s * C_OUT + c) * LDF + v * 4);
                m.x = fmaxf(m.x, t.x); m.y = fmaxf(m.y, t.y);
                m.z = fmaxf(m.z, t.z); m.w = fmaxf(m.w, t.w);
            }
        }
        out[v] = m;
    }
}

// ---------------- fused SAGE GEMM: out = agg@Wl^T + h@Wr^T + b -------------------
// NT gemm, both operands K-contiguous with LDF stride. BM=BN=128, BK=8, 8x8/thread.
// K loop runs 164 tiles: phase 0 = (agg, Wl), phase 1 = (h, Wr). Double-buffered.
__global__ void __launch_bounds__(256, 2) sage_gemm(int src, const float* __restrict__ bias) {
    __shared__ float As[2][8][128];
    __shared__ float Bs[2][8][128];
    const float* H   = src ? g_bufB : g_bufA;
    float*       Out = src ? g_bufA : g_bufB;
    const float* Ap[2] = {g_agg, H};
    const float* Bp[2] = {g_wl, g_wr};

    const int tid = threadIdx.x;
    const int m0 = blockIdx.x * 128;
    const int n0 = blockIdx.y * 128;
    const int lr = tid >> 1;          // row within tile for loads
    const int lc = (tid & 1) * 4;     // k offset for loads
    const int tx = tid & 15;
    const int ty = tid >> 4;

    float acc[8][8];
#pragma unroll
    for (int i = 0; i < 8; i++)
#pragma unroll
        for (int j = 0; j < 8; j++) acc[i][j] = 0.f;

    // prologue: load first tile (phase 0, k0 = 0)
    {
        float4 a4 = *(const float4*)(Ap[0] + (size_t)(m0 + lr) * LDF + lc);
        float4 b4 = *(const float4*)(Bp[0] + (size_t)(n0 + lr) * LDF + lc);
        As[0][lc + 0][lr] = a4.x; As[0][lc + 1][lr] = a4.y;
        As[0][lc + 2][lr] = a4.z; As[0][lc + 3][lr] = a4.w;
        Bs[0][lc + 0][lr] = b4.x; Bs[0][lc + 1][lr] = b4.y;
        Bs[0][lc + 2][lr] = b4.z; Bs[0][lc + 3][lr] = b4.w;
    }
    __syncthreads();

    const int STEPS = 2 * KTILES;  // 164
    int buf = 0;
    for (int s = 0; s < STEPS; s++) {
        int ns = s + 1;
        bool hasNext = ns < STEPS;
        float4 na, nb;
        if (hasNext) {
            int ph = (ns >= KTILES) ? 1 : 0;
            int k0 = (ns - ph * KTILES) * 8;
            na = *(const float4*)(Ap[ph] + (size_t)(m0 + lr) * LDF + k0 + lc);
            nb = *(const float4*)(Bp[ph] + (size_t)(n0 + lr) * LDF + k0 + lc);
        }
#pragma unroll
        for (int k = 0; k < 8; k++) {
            float4 a0 = *(const float4*)&As[buf][k][ty * 8];
            float4 a1 = *(const float4*)&As[buf][k][ty * 8 + 4];
            float4 b0 = *(const float4*)&Bs[buf][k][tx * 8];
            float4 b1 = *(const float4*)&Bs[buf][k][tx * 8 + 4];
            float ar[8] = {a0.x, a0.y, a0.z, a0.w, a1.x, a1.y, a1.z, a1.w};
            float br[8] = {b0.x, b0.y, b0.z, b0.w, b1.x, b1.y, b1.z, b1.w};
#pragma unroll
            for (int i = 0; i < 8; i++)
#pragma unroll
                for (int j = 0; j < 8; j++)
                    acc[i][j] = fmaf(ar[i], br[j], acc[i][j]);
        }
        if (hasNext) {
            int nbuf = buf ^ 1;
            As[nbuf][lc + 0][lr] = na.x; As[nbuf][lc + 1][lr] = na.y;
            As[nbuf][lc + 2][lr] = na.z; As[nbuf][lc + 3][lr] = na.w;
            Bs[nbuf][lc + 0][lr] = nb.x; Bs[nbuf][lc + 1][lr] = nb.y;
            Bs[nbuf][lc + 2][lr] = nb.z; Bs[nbuf][lc + 3][lr] = nb.w;
        }
        __syncthreads();
        buf ^= 1;
    }

    // epilogue: add bias, write (zero the padded tail columns so next layer is clean)
#pragma unroll
    for (int i = 0; i < 8; i++) {
        int row = m0 + ty * 8 + i;
        float* orow = Out + (size_t)row * LDF;
#pragma unroll
        for (int j = 0; j < 8; j++) {
            int col = n0 + tx * 8 + j;
            if (col < F_DIM)      orow[col] = acc[i][j] + bias[col];
            else if (col < LDF)   orow[col] = 0.f;
        }
    }
}

// ---------------- mean pool over nodes: [116,256,LDF] -> g_mean [256,LDF] --------
__global__ void mean_pool(int src) {
    const float* h = src ? g_bufB : g_bufA;
    int idx = blockIdx.x * blockDim.x + threadIdx.x;
    if (idx >= C_OUT * LDF) return;
    int c = idx / LDF, f = idx % LDF;
    float s = 0.f;
    for (int n = 0; n < N_NODES; n++)
        s += h[((size_t)n * C_OUT + c) * LDF + f];
    g_mean[idx] = s * (1.f / N_NODES);
}

__device__ __forceinline__ float gelu_exact(float x) {
    return 0.5f * x * (1.f + erff(x * 0.70710678118654752f));
}

// ---------------- fc1 + gelu: [256,653] x [128,653]^T -> g_fc1 [256,128] ---------
__global__ void fc1_kernel(const float* __restrict__ w, const float* __restrict__ b) {
    __shared__ float row[F_DIM];
    int c = blockIdx.x;
    int tid = threadIdx.x;
    for (int f = tid; f < F_DIM; f += blockDim.x) row[f] = g_mean[c * LDF + f];
    __syncthreads();
    int warp = tid >> 5, lane = tid & 31;
    for (int g = warp; g < 128; g += blockDim.x / 32) {
        const float* wr = w + (size_t)g * F_DIM;
        float acc = 0.f;
        for (int f = lane; f < F_DIM; f += 32) acc = fmaf(row[f], wr[f], acc);
#pragma unroll
        for (int o = 16; o; o >>= 1) acc += __shfl_xor_sync(0xffffffffu, acc, o);
        if (lane == 0) g_fc1[c * 128 + g] = gelu_exact(acc + b[g]);
    }
}

// ---------------- fc2 + gelu + fc3 + softmax: -> out [256,4] ---------------------
__global__ void head_kernel(const float* __restrict__ f2w, const float* __restrict__ f2b,
                            const float* __restrict__ f3w, const float* __restrict__ f3b,
                            float* __restrict__ out) {
    __shared__ float r1[128];
    __shared__ float r2[32];
    __shared__ float r3[4];
    int c = blockIdx.x;
    int tid = threadIdx.x;  // 32 threads
    for (int i = tid; i < 128; i += 32) r1[i] = g_fc1[c * 128 + i];
    __syncthreads();
    {
        float acc = f2b[tid];
        const float* wr = f2w + (size_t)tid * 128;
        for (int f = 0; f < 128; f++) acc = fmaf(r1[f], wr[f], acc);
        r2[tid] = gelu_exact(acc);
    }
    __syncthreads();
    if (tid < 4) {
        float a = f3b[tid];
        const float* wr = f3w + (size_t)tid * 32;
        for (int f = 0; f < 32; f++) a = fmaf(r2[f], wr[f], a);
        r3[tid] = a;
    }
    __syncthreads();
    if (tid == 0) {
        float mx = fmaxf(fmaxf(r3[0], r3[1]), fmaxf(r3[2], r3[3]));
        float e0 = expf(r3[0] - mx), e1 = expf(r3[1] - mx);
        float e2 = expf(r3[2] - mx), e3 = expf(r3[3] - mx);
        float inv = 1.f / (e0 + e1 + e2 + e3);
        out[c * 4 + 0] = e0 * inv;
        out[c * 4 + 1] = e1 * inv;
        out[c * 4 + 2] = e2 * inv;
        out[c * 4 + 3] = e3 * inv;
    }
}

// ---------------- launch ---------------------------------------------------------
extern "C" void kernel_launch(void* const* d_in, const int* in_sizes, int n_in,
                              void* d_out, int out_size) {
    const float* x      = (const float*)d_in[0];
    const int*   ei     = (const int*)d_in[1];
    const float* conv_w = (const float*)d_in[2];
    const float* conv_b = (const float*)d_in[3];
    const float* wl     = (const float*)d_in[4];
    const float* wr     = (const float*)d_in[5];
    const float* sb     = (const float*)d_in[6];
    const float* f1w    = (const float*)d_in[7];
    const float* f1b    = (const float*)d_in[8];
    const float* f2w    = (const float*)d_in[9];
    const float* f2b    = (const float*)d_in[10];
    const float* f3w    = (const float*)d_in[11];
    const float* f3b    = (const float*)d_in[12];
    float* out = (float*)d_out;

    cudaFuncSetAttribute(conv1d_grouped,
                         cudaFuncAttributeMaxDynamicSharedMemorySize, CONV_SMEM);

    build_csr<<<1, 128>>>(ei);
    pad_weights<<<(NPAD * LDF + 255) / 256, 256>>>(wl, wr);
    conv1d_grouped<<<dim3(N_NODES, 4), 256, CONV_SMEM>>>(x, conv_w, conv_b);

    // 3 SAGE layers, ping-pong A<->B.  layer0: A->B, layer1: B->A, layer2: A->B
    for (int l = 0; l < 3; l++) {
        int src = l & 1;
        sage_agg<<<M_ROWS, 128>>>(src);
        sage_gemm<<<dim3(M_ROWS / 128, NPAD / 128), 256>>>(src, sb);
    }

    mean_pool<<<(C_OUT * LDF + 255) / 256, 256>>>(1 /* final result lives in bufB */);
    fc1_kernel<<<256, 128>>>(f1w, f1b);
    head_kernel<<<256, 32>>>(f2w, f2b, f3w, f3b, out);
}

// round 6
// speedup vs baseline: 1.4327x; 1.4269x over previous
#include <cuda_runtime.h>
#include <cuda_bf16.h>
#include <mma.h>
#include <math.h>
#include <stdint.h>

using namespace nvcuda;

#define N_NODES 116
#define N_EDGES 1160
#define C_IN    64
#define T_IN    657
#define C_OUT   256
#define F_DIM   653
#define LDF     656                 // fp32 row stride
#define M_ROWS  (N_NODES * C_OUT)   // 29696
#define M_TILES 232                 // 29696/128
#define N_TILES 6                   // 768/128
#define NPAD    768
#define LKB     672                 // bf16 row stride (padded K, mult of 32)
#define KT_PHASE 21                 // 672/32
#define KT_TOTAL 42

#define BK      32
#define STAGE_B 32768               // Ah 8K + Al 8K + Bh 8K + Bl 8K
#define STAGES  3
#define GEMM_SMEM (STAGES * STAGE_B)   // 98304; epilogue reuses (128*132*4 = 67584)

// single consistent dynamic-smem declaration for ALL kernels
extern __shared__ __align__(128) unsigned char dyn_smem[];

// ---------------- device scratch --------------------------------------------
__device__ __align__(16) float g_bufA[(size_t)M_ROWS * LDF];
__device__ __align__(16) float g_bufB[(size_t)M_ROWS * LDF];
__device__ __align__(16) __nv_bfloat16 g_aggh[(size_t)M_ROWS * LKB];
__device__ __align__(16) __nv_bfloat16 g_aggl[(size_t)M_ROWS * LKB];
__device__ __align__(16) __nv_bfloat16 g_hh0[(size_t)M_ROWS * LKB];
__device__ __align__(16) __nv_bfloat16 g_hl0[(size_t)M_ROWS * LKB];
__device__ __align__(16) __nv_bfloat16 g_hh1[(size_t)M_ROWS * LKB];
__device__ __align__(16) __nv_bfloat16 g_hl1[(size_t)M_ROWS * LKB];
__device__ __align__(16) __nv_bfloat16 g_wlh[(size_t)NPAD * LKB];
__device__ __align__(16) __nv_bfloat16 g_wll[(size_t)NPAD * LKB];
__device__ __align__(16) __nv_bfloat16 g_wrh[(size_t)NPAD * LKB];
__device__ __align__(16) __nv_bfloat16 g_wrl[(size_t)NPAD * LKB];
__device__ int   g_offs[N_NODES + 1];
__device__ int   g_list[N_EDGES];
__device__ float g_mean[C_OUT * LDF];
__device__ float g_fc1 [C_OUT * 128];

// ---------------- helpers -----------------------------------------------------
__device__ __forceinline__ uint32_t smem_u32(const void* p) {
    uint32_t a;
    asm("{ .reg .u64 t; cvta.to.shared.u64 t, %1; cvt.u32.u64 %0, t; }" : "=r"(a) : "l"(p));
    return a;
}
__device__ __forceinline__ void cpa16(uint32_t dst, const void* src) {
    asm volatile("cp.async.cg.shared.global [%0], [%1], 16;" :: "r"(dst), "l"(src));
}
#define CP_COMMIT() asm volatile("cp.async.commit_group;" ::: "memory")
#define CP_WAIT1()  asm volatile("cp.async.wait_group 1;" ::: "memory")

__device__ __forceinline__ void bsplit(float v, uint16_t& h, uint16_t& l) {
    __nv_bfloat16 hb = __float2bfloat16(v);
    __nv_bfloat16 lb = __float2bfloat16(v - __bfloat162float(hb));
    h = __bfloat16_as_ushort(hb);
    l = __bfloat16_as_ushort(lb);
}
__device__ __forceinline__ uint2 pack4(uint16_t a, uint16_t b, uint16_t c, uint16_t d) {
    uint2 r;
    r.x = (uint32_t)a | ((uint32_t)b << 16);
    r.y = (uint32_t)c | ((uint32_t)d << 16);
    return r;
}

// ---------------- CSR build (edge_index arrives as int32) ---------------------
__global__ void build_csr(const int* __restrict__ ei) {
    __shared__ int cnt[N_NODES + 1];
    __shared__ int offs[N_NODES + 1];
    int tid = threadIdx.x;
    for (int i = tid; i <= N_NODES; i += blockDim.x) cnt[i] = 0;
    __syncthreads();
    for (int e = tid; e < N_EDGES; e += blockDim.x) {
        int dst = min(max(ei[N_EDGES + e], 0), N_NODES - 1);
        atomicAdd(&cnt[dst], 1);
    }
    __syncthreads();
    if (tid == 0) {
        int s = 0;
        for (int i = 0; i < N_NODES; i++) { offs[i] = s; s += cnt[i]; }
        offs[N_NODES] = s;
    }
    __syncthreads();
    for (int i = tid; i <= N_NODES; i += blockDim.x) { g_offs[i] = offs[i]; cnt[i] = offs[i]; }
    __syncthreads();
    for (int e = tid; e < N_EDGES; e += blockDim.x) {
        int src = min(max(ei[e], 0), N_NODES - 1);
        int dst = min(max(ei[N_EDGES + e], 0), N_NODES - 1);
        int pos = atomicAdd(&cnt[dst], 1);
        if (pos >= 0 && pos < N_EDGES) g_list[pos] = src;
    }
}

// ---------------- weight convert -> row-major bf16 hi/lo [768][672] -----------
__global__ void conv_weights(const float* __restrict__ wl, const float* __restrict__ wr) {
    int idx = blockIdx.x * blockDim.x + threadIdx.x;   // over 768 * 168 quads
    if (idx >= NPAD * (LKB / 4)) return;
    int nrow = idx / (LKB / 4);
    int k0   = (idx % (LKB / 4)) * 4;
    size_t off = (size_t)nrow * LKB + k0;
    uint16_t lh[4], ll[4], rh[4], rl[4];
#pragma unroll
    for (int e = 0; e < 4; e++) {
        int k = k0 + e;
        float a = (nrow < F_DIM && k < F_DIM) ? wl[(size_t)nrow * F_DIM + k] : 0.f;
        float b = (nrow < F_DIM && k < F_DIM) ? wr[(size_t)nrow * F_DIM + k] : 0.f;
        bsplit(a, lh[e], ll[e]);
        bsplit(b, rh[e], rl[e]);
    }
    *(uint2*)(g_wlh + off) = pack4(lh[0], lh[1], lh[2], lh[3]);
    *(uint2*)(g_wll + off) = pack4(ll[0], ll[1], ll[2], ll[3]);
    *(uint2*)(g_wrh + off) = pack4(rh[0], rh[1], rh[2], rh[3]);
    *(uint2*)(g_wrl + off) = pack4(rl[0], rl[1], rl[2], rl[3]);
}

// ---------------- grouped Conv1d -> bufA (fp32) + hh0/hl0 (bf16) --------------
#define XS_STRIDE 660
#define CONV_SMEM ((16 * XS_STRIDE + 64 * 80) * 4)
__global__ void conv1d_grouped(const float* __restrict__ x,
                               const float* __restrict__ w,
                               const float* __restrict__ b) {
    float* smem = (float*)dyn_smem;
    float* xs = smem;
    float* ws = smem + 16 * XS_STRIDE;
    int n = blockIdx.x, g = blockIdx.y;
    int tid = threadIdx.x;

    const float* xbase = x + ((size_t)n * C_IN + (size_t)g * 16) * T_IN;
    for (int i = tid; i < 16 * T_IN; i += blockDim.x) {
        int ic = i / T_IN, t = i % T_IN;
        xs[ic * XS_STRIDE + t] = xbase[i];
    }
    for (int i = tid; i < 64 * 80; i += blockDim.x)
        ws[i] = w[(size_t)g * 64 * 80 + i];
    __syncthreads();

    for (int task = tid; task < 64 * 164; task += blockDim.x) {
        int oc = task / 164;
        int t0 = (task % 164) * 4;
        float bias = b[g * 64 + oc];
        float a0 = bias, a1 = bias, a2 = bias, a3 = bias;
        const float* wrow = &ws[oc * 80];
#pragma unroll
        for (int i = 0; i < 16; i++) {
            float4 x0 = *(const float4*)&xs[i * XS_STRIDE + t0];
            float4 x1 = *(const float4*)&xs[i * XS_STRIDE + t0 + 4];
            float xv[8] = {x0.x, x0.y, x0.z, x0.w, x1.x, x1.y, x1.z, x1.w};
#pragma unroll
            for (int k = 0; k < 5; k++) {
                float wv = wrow[i * 5 + k];
                a0 = fmaf(xv[0 + k], wv, a0);
                a1 = fmaf(xv[1 + k], wv, a1);
                a2 = fmaf(xv[2 + k], wv, a2);
                a3 = fmaf(xv[3 + k], wv, a3);
            }
        }
        float z0 = (t0 + 0 < F_DIM) ? a0 : 0.f;
        float z1 = (t0 + 1 < F_DIM) ? a1 : 0.f;
        float z2 = (t0 + 2 < F_DIM) ? a2 : 0.f;
        float z3 = (t0 + 3 < F_DIM) ? a3 : 0.f;
        int row = n * C_OUT + g * 64 + oc;
        float* out = &g_bufA[(size_t)row * LDF + t0];
        out[0] = z0; out[1] = z1; out[2] = z2; out[3] = z3;
        uint16_t h[4], l[4];
        bsplit(z0, h[0], l[0]); bsplit(z1, h[1], l[1]);
        bsplit(z2, h[2], l[2]); bsplit(z3, h[3], l[3]);
        size_t off = (size_t)row * LKB + t0;
        *(uint2*)(g_hh0 + off) = pack4(h[0], h[1], h[2], h[3]);
        *(uint2*)(g_hl0 + off) = pack4(l[0], l[1], l[2], l[3]);
    }
    // zero the bf16 K-pad tail (cols 656..671) for this block's 64 rows
    for (int i = tid; i < 64 * 4; i += blockDim.x) {
        int oc = i / 4;
        int c0 = 656 + (i % 4) * 4;
        int row = n * C_OUT + g * 64 + oc;
        size_t off = (size_t)row * LKB + c0;
        *(uint2*)(g_hh0 + off) = make_uint2(0u, 0u);
        *(uint2*)(g_hl0 + off) = make_uint2(0u, 0u);
    }
}

// ---------------- SAGE max-aggregation -> aggh/aggl (bf16 row-major) ----------
__global__ void sage_agg(int src) {
    const float* h = src ? g_bufB : g_bufA;
    int row = blockIdx.x;          // n*256 + c
    int n = row >> 8;
    int c = row & 255;
    int beg = g_offs[n], end = g_offs[n + 1];
    size_t obase = (size_t)row * LKB;
    for (int v = threadIdx.x; v < LKB / 4; v += blockDim.x) {
        int f0 = v * 4;
        float4 m = make_float4(0.f, 0.f, 0.f, 0.f);
        if (f0 < LDF && end > beg) {
            m = make_float4(-3.4e38f, -3.4e38f, -3.4e38f, -3.4e38f);
            for (int e = beg; e < end; e++) {
                int s = g_list[e];
                float4 t = *(const float4*)(h + ((size_t)s * C_OUT + c) * LDF + f0);
                m.x = fmaxf(m.x, t.x); m.y = fmaxf(m.y, t.y);
                m.z = fmaxf(m.z, t.z); m.w = fmaxf(m.w, t.w);
            }
        }
        uint16_t hh[4], ll[4];
        bsplit(m.x, hh[0], ll[0]); bsplit(m.y, hh[1], ll[1]);
        bsplit(m.z, hh[2], ll[2]); bsplit(m.w, hh[3], ll[3]);
        *(uint2*)(g_aggh + obase + f0) = pack4(hh[0], hh[1], hh[2], hh[3]);
        *(uint2*)(g_aggl + obase + f0) = pack4(ll[0], ll[1], ll[2], ll[3]);
    }
}

// ---------------- WMMA fused SAGE GEMM ----------------------------------------
// C[128x128] = agg@Wl^T + h@Wr^T (3-term bf16 split), bias added in epilogue.
__device__ __forceinline__ void stage_copy(uint32_t sbase, int tid,
                                           const __nv_bfloat16* pAh, const __nv_bfloat16* pAl,
                                           const __nv_bfloat16* pBh, const __nv_bfloat16* pBl) {
#pragma unroll
    for (int half = 0; half < 2; half++) {
        int c = tid + half * 256;       // 0..511
        int row = c >> 2;               // 0..127
        int col = (c & 3) << 3;         // 0,8,16,24
        uint32_t so = (uint32_t)(row * BK + col) * 2;
        size_t go = (size_t)row * LKB + col;
        cpa16(sbase +         so, pAh + go);
        cpa16(sbase +  8192 + so, pAl + go);
        cpa16(sbase + 16384 + so, pBh + go);
        cpa16(sbase + 24576 + so, pBl + go);
    }
    CP_COMMIT();
}

__global__ void __launch_bounds__(256, 1) sage_gemm(int src, int writeB,
                                                    const float* __restrict__ bias) {
    __shared__ float sbias[128];
    const int tid = threadIdx.x;
    const int wid = tid >> 5;
    const int m0 = blockIdx.x * 128;
    const int n0 = blockIdx.y * 128;

    const __nv_bfloat16* AhArr[2] = { g_aggh, src ? g_hh1 : g_hh0 };
    const __nv_bfloat16* AlArr[2] = { g_aggl, src ? g_hl1 : g_hl0 };
    const __nv_bfloat16* BhArr[2] = { g_wlh, g_wrh };
    const __nv_bfloat16* BlArr[2] = { g_wll, g_wrl };
    float*          Out  = src ? g_bufA : g_bufB;
    __nv_bfloat16*  OutH = src ? g_hh0 : g_hh1;
    __nv_bfloat16*  OutL = src ? g_hl0 : g_hl1;

    if (tid < 128) {
        int cg = n0 + tid;
        sbias[tid] = (cg < F_DIM) ? bias[cg] : 0.f;
    }

    const uint32_t smem_base = smem_u32(dyn_smem);

    // prologue: stages 0,1
#pragma unroll
    for (int p = 0; p < 2; p++) {
        int ph = 0; int k0 = p * BK;   // first two chunks are both phase 0
        stage_copy(smem_base + p * STAGE_B, tid,
                   AhArr[ph] + (size_t)m0 * LKB + k0,
                   AlArr[ph] + (size_t)m0 * LKB + k0,
                   BhArr[ph] + (size_t)n0 * LKB + k0,
                   BlArr[ph] + (size_t)n0 * LKB + k0);
    }

    const int wm = (wid & 3) * 32;      // warp m offset within tile
    const int wn = (wid >> 2) * 64;     // warp n offset within tile

    wmma::fragment<wmma::accumulator, 16, 16, 16, float> acc[2][4];
#pragma unroll
    for (int i = 0; i < 2; i++)
#pragma unroll
        for (int j = 0; j < 4; j++) wmma::fill_fragment(acc[i][j], 0.f);

    for (int kt = 0; kt < KT_TOTAL; kt++) {
        CP_WAIT1();
        __syncthreads();
        int nk = kt + 2;
        if (nk < KT_TOTAL) {
            int ph = (nk >= KT_PHASE) ? 1 : 0;
            int k0 = (nk - ph * KT_PHASE) * BK;
            stage_copy(smem_base + (nk % STAGES) * STAGE_B, tid,
                       AhArr[ph] + (size_t)m0 * LKB + k0,
                       AlArr[ph] + (size_t)m0 * LKB + k0,
                       BhArr[ph] + (size_t)n0 * LKB + k0,
                       BlArr[ph] + (size_t)n0 * LKB + k0);
        } else {
            CP_COMMIT();
        }
        const __nv_bfloat16* sA = (const __nv_bfloat16*)(dyn_smem + (kt % STAGES) * STAGE_B);
        const __nv_bfloat16* sB = sA + 8192;   // elements: Ah 0..4095, Al 4096.., Bh 8192.., Bl 12288..
#pragma unroll
        for (int ks = 0; ks < 2; ks++) {
            wmma::fragment<wmma::matrix_a, 16, 16, 16, __nv_bfloat16, wmma::row_major> ah[2], al[2];
            wmma::fragment<wmma::matrix_b, 16, 16, 16, __nv_bfloat16, wmma::col_major> bh[4], bl[4];
#pragma unroll
            for (int i = 0; i < 2; i++) {
                const __nv_bfloat16* pa = sA + (wm + i * 16) * BK + ks * 16;
                wmma::load_matrix_sync(ah[i], pa, BK);
                wmma::load_matrix_sync(al[i], pa + 4096, BK);
            }
#pragma unroll
            for (int j = 0; j < 4; j++) {
                const __nv_bfloat16* pb = sB + (wn + j * 16) * BK + ks * 16;
                wmma::load_matrix_sync(bh[j], pb, BK);
                wmma::load_matrix_sync(bl[j], pb + 4096, BK);
            }
#pragma unroll
            for (int i = 0; i < 2; i++)
#pragma unroll
                for (int j = 0; j < 4; j++) {
                    wmma::mma_sync(acc[i][j], ah[i], bh[j], acc[i][j]);
                    wmma::mma_sync(acc[i][j], al[i], bh[j], acc[i][j]);
                    wmma::mma_sync(acc[i][j], ah[i], bl[j], acc[i][j]);
                }
        }
    }

    // epilogue: stage accumulators through smem (reuse pipeline smem)
    __syncthreads();
    float* Cs = (float*)dyn_smem;       // [128][132]
#pragma unroll
    for (int i = 0; i < 2; i++)
#pragma unroll
        for (int j = 0; j < 4; j++)
            wmma::store_matrix_sync(&Cs[(wm + i * 16) * 132 + wn + j * 16], acc[i][j],
                                    132, wmma::mem_row_major);
    __syncthreads();

#pragma unroll
    for (int t = 0; t < 16; t++) {
        int q = tid + t * 256;          // 0..4095
        int row = q >> 5;
        int col = (q & 31) * 4;
        float v0 = Cs[row * 132 + col + 0] + sbias[col + 0];
        float v1 = Cs[row * 132 + col + 1] + sbias[col + 1];
        float v2 = Cs[row * 132 + col + 2] + sbias[col + 2];
        float v3 = Cs[row * 132 + col + 3] + sbias[col + 3];
        int cg = n0 + col;
        int m = m0 + row;
        if (cg < LDF) {
            *(float4*)(Out + (size_t)m * LDF + cg) = make_float4(v0, v1, v2, v3);
        }
        if (writeB && cg < LKB) {
            uint16_t h[4], l[4];
            bsplit(v0, h[0], l[0]); bsplit(v1, h[1], l[1]);
            bsplit(v2, h[2], l[2]); bsplit(v3, h[3], l[3]);
            size_t off = (size_t)m * LKB + cg;
            *(uint2*)(OutH + off) = pack4(h[0], h[1], h[2], h[3]);
            *(uint2*)(OutL + off) = pack4(l[0], l[1], l[2], l[3]);
        }
    }
}

// ---------------- mean pool -> g_mean ------------------------------------------
__global__ void mean_pool(int src) {
    const float* h = src ? g_bufB : g_bufA;
    int idx = blockIdx.x * blockDim.x + threadIdx.x;
    if (idx >= C_OUT * LDF) return;
    int c = idx / LDF, f = idx % LDF;
    float s = 0.f;
    for (int n = 0; n < N_NODES; n++)
        s += h[((size_t)n * C_OUT + c) * LDF + f];
    g_mean[idx] = s * (1.f / N_NODES);
}

__device__ __forceinline__ float gelu_exact(float x) {
    return 0.5f * x * (1.f + erff(x * 0.70710678118654752f));
}

// ---------------- fc1 + gelu ----------------------------------------------------
__global__ void fc1_kernel(const float* __restrict__ w, const float* __restrict__ b) {
    __shared__ float row[F_DIM];
    int c = blockIdx.x;
    int tid = threadIdx.x;
    for (int f = tid; f < F_DIM; f += blockDim.x) row[f] = g_mean[c * LDF + f];
    __syncthreads();
    int warp = tid >> 5, lane = tid & 31;
    for (int g = warp; g < 128; g += blockDim.x / 32) {
        const float* wr = w + (size_t)g * F_DIM;
        float acc = 0.f;
        for (int f = lane; f < F_DIM; f += 32) acc = fmaf(row[f], wr[f], acc);
#pragma unroll
        for (int o = 16; o; o >>= 1) acc += __shfl_xor_sync(0xffffffffu, acc, o);
        if (lane == 0) g_fc1[c * 128 + g] = gelu_exact(acc + b[g]);
    }
}

// ---------------- fc2 + gelu + fc3 + softmax ------------------------------------
__global__ void head_kernel(const float* __restrict__ f2w, const float* __restrict__ f2b,
                            const float* __restrict__ f3w, const float* __restrict__ f3b,
                            float* __restrict__ out) {
    __shared__ float r1[128];
    __shared__ float r2[32];
    __shared__ float r3[4];
    int c = blockIdx.x;
    int tid = threadIdx.x;
    for (int i = tid; i < 128; i += 32) r1[i] = g_fc1[c * 128 + i];
    __syncthreads();
    {
        float acc = f2b[tid];
        const float* wr = f2w + (size_t)tid * 128;
        for (int f = 0; f < 128; f++) acc = fmaf(r1[f], wr[f], acc);
        r2[tid] = gelu_exact(acc);
    }
    __syncthreads();
    if (tid < 4) {
        float a = f3b[tid];
        const float* wr = f3w + (size_t)tid * 32;
        for (int f = 0; f < 32; f++) a = fmaf(r2[f], wr[f], a);
        r3[tid] = a;
    }
    __syncthreads();
    if (tid == 0) {
        float mx = fmaxf(fmaxf(r3[0], r3[1]), fmaxf(r3[2], r3[3]));
        float e0 = expf(r3[0] - mx), e1 = expf(r3[1] - mx);
        float e2 = expf(r3[2] - mx), e3 = expf(r3[3] - mx);
        float inv = 1.f / (e0 + e1 + e2 + e3);
        out[c * 4 + 0] = e0 * inv;
        out[c * 4 + 1] = e1 * inv;
        out[c * 4 + 2] = e2 * inv;
        out[c * 4 + 3] = e3 * inv;
    }
}

// ---------------- launch --------------------------------------------------------
extern "C" void kernel_launch(void* const* d_in, const int* in_sizes, int n_in,
                              void* d_out, int out_size) {
    const float* x      = (const float*)d_in[0];
    const int*   ei     = (const int*)d_in[1];
    const float* conv_w = (const float*)d_in[2];
    const float* conv_b = (const float*)d_in[3];
    const float* wl     = (const float*)d_in[4];
    const float* wr     = (const float*)d_in[5];
    const float* sb     = (const float*)d_in[6];
    const float* f1w    = (const float*)d_in[7];
    const float* f1b    = (const float*)d_in[8];
    const float* f2w    = (const float*)d_in[9];
    const float* f2b    = (const float*)d_in[10];
    const float* f3w    = (const float*)d_in[11];
    const float* f3b    = (const float*)d_in[12];
    float* out = (float*)d_out;

    cudaFuncSetAttribute(conv1d_grouped, cudaFuncAttributeMaxDynamicSharedMemorySize, CONV_SMEM);
    cudaFuncSetAttribute(sage_gemm,      cudaFuncAttributeMaxDynamicSharedMemorySize, GEMM_SMEM);

    build_csr<<<1, 128>>>(ei);
    conv_weights<<<(NPAD * (LKB / 4) + 255) / 256, 256>>>(wl, wr);
    conv1d_grouped<<<dim3(N_NODES, 4), 256, CONV_SMEM>>>(x, conv_w, conv_b);

    // 3 SAGE layers. l0: A->B (h: hh0 -> hh1), l1: B->A (hh1 -> hh0), l2: A->B
    for (int l = 0; l < 3; l++) {
        int src = l & 1;
        sage_agg<<<M_ROWS, 128>>>(src);
        sage_gemm<<<dim3(M_TILES, N_TILES), 256, GEMM_SMEM>>>(src, l < 2 ? 1 : 0, sb);
    }

    mean_pool<<<(C_OUT * LDF + 255) / 256, 256>>>(1);
    fc1_kernel<<<256, 128>>>(f1w, f1b);
    head_kernel<<<256, 32>>>(f2w, f2b, f3w, f3b, out);
}

// round 7
// speedup vs baseline: 2.4527x; 1.7119x over previous
#include <cuda_runtime.h>
#include <cuda_bf16.h>
#include <mma.h>
#include <math.h>
#include <stdint.h>

using namespace nvcuda;

#define N_NODES 116
#define N_EDGES 1160
#define C_IN    64
#define T_IN    657
#define C_OUT   256
#define F_DIM   653
#define LDF     656                 // fp32 row stride
#define M_ROWS  (N_NODES * C_OUT)   // 29696
#define M_TILES 232                 // 29696/128
#define N_TILES 6                   // 768/128
#define NPAD    768
#define LKB     672                 // bf16 row stride (padded K, mult of 32)
#define KT_PHASE 21                 // 672/32
#define KT_TOTAL 42

#define BK      32
#define SROW    56                  // padded smem row (bf16 elems): 112B -> conflict-free LDSM
#define MAT_B   (128 * SROW * 2)    // 14336 bytes per matrix tile
#define STAGE_B (4 * MAT_B)         // 57344: Ah, Al, Bh, Bl
#define STAGES  2
#define GEMM_SMEM (STAGES * STAGE_B)   // 114688; epilogue reuses (128*132*4 = 67584)

// element offsets within a stage (bf16 units)
#define OFF_AL  7168
#define OFF_BH  14336
#define OFF_BL  21504

// single consistent dynamic-smem declaration for ALL kernels
extern __shared__ __align__(128) unsigned char dyn_smem[];

// ---------------- device scratch --------------------------------------------
__device__ __align__(16) float g_bufA[(size_t)M_ROWS * LDF];
__device__ __align__(16) float g_bufB[(size_t)M_ROWS * LDF];
__device__ __align__(16) __nv_bfloat16 g_aggh[(size_t)M_ROWS * LKB];
__device__ __align__(16) __nv_bfloat16 g_aggl[(size_t)M_ROWS * LKB];
__device__ __align__(16) __nv_bfloat16 g_hh0[(size_t)M_ROWS * LKB];
__device__ __align__(16) __nv_bfloat16 g_hl0[(size_t)M_ROWS * LKB];
__device__ __align__(16) __nv_bfloat16 g_hh1[(size_t)M_ROWS * LKB];
__device__ __align__(16) __nv_bfloat16 g_hl1[(size_t)M_ROWS * LKB];
__device__ __align__(16) __nv_bfloat16 g_wlh[(size_t)NPAD * LKB];
__device__ __align__(16) __nv_bfloat16 g_wll[(size_t)NPAD * LKB];
__device__ __align__(16) __nv_bfloat16 g_wrh[(size_t)NPAD * LKB];
__device__ __align__(16) __nv_bfloat16 g_wrl[(size_t)NPAD * LKB];
__device__ int   g_offs[N_NODES + 1];
__device__ int   g_list[N_EDGES];
__device__ float g_mean[C_OUT * LDF];
__device__ float g_fc1 [C_OUT * 128];

// ---------------- helpers -----------------------------------------------------
__device__ __forceinline__ uint32_t smem_u32(const void* p) {
    uint32_t a;
    asm("{ .reg .u64 t; cvta.to.shared.u64 t, %1; cvt.u32.u64 %0, t; }" : "=r"(a) : "l"(p));
    return a;
}
__device__ __forceinline__ void cpa16(uint32_t dst, const void* src) {
    asm volatile("cp.async.cg.shared.global [%0], [%1], 16;" :: "r"(dst), "l"(src));
}
#define CP_COMMIT() asm volatile("cp.async.commit_group;" ::: "memory")
#define CP_WAIT1()  asm volatile("cp.async.wait_group 1;" ::: "memory")

__device__ __forceinline__ void bsplit(float v, uint16_t& h, uint16_t& l) {
    __nv_bfloat16 hb = __float2bfloat16(v);
    __nv_bfloat16 lb = __float2bfloat16(v - __bfloat162float(hb));
    h = __bfloat16_as_ushort(hb);
    l = __bfloat16_as_ushort(lb);
}
__device__ __forceinline__ uint2 pack4(uint16_t a, uint16_t b, uint16_t c, uint16_t d) {
    uint2 r;
    r.x = (uint32_t)a | ((uint32_t)b << 16);
    r.y = (uint32_t)c | ((uint32_t)d << 16);
    return r;
}

// ---------------- CSR build (edge_index arrives as int32) ---------------------
__global__ void build_csr(const int* __restrict__ ei) {
    __shared__ int cnt[N_NODES + 1];
    __shared__ int offs[N_NODES + 1];
    int tid = threadIdx.x;
    for (int i = tid; i <= N_NODES; i += blockDim.x) cnt[i] = 0;
    __syncthreads();
    for (int e = tid; e < N_EDGES; e += blockDim.x) {
        int dst = min(max(ei[N_EDGES + e], 0), N_NODES - 1);
        atomicAdd(&cnt[dst], 1);
    }
    __syncthreads();
    if (tid == 0) {
        int s = 0;
        for (int i = 0; i < N_NODES; i++) { offs[i] = s; s += cnt[i]; }
        offs[N_NODES] = s;
    }
    __syncthreads();
    for (int i = tid; i <= N_NODES; i += blockDim.x) { g_offs[i] = offs[i]; cnt[i] = offs[i]; }
    __syncthreads();
    for (int e = tid; e < N_EDGES; e += blockDim.x) {
        int src = min(max(ei[e], 0), N_NODES - 1);
        int dst = min(max(ei[N_EDGES + e], 0), N_NODES - 1);
        int pos = atomicAdd(&cnt[dst], 1);
        if (pos >= 0 && pos < N_EDGES) g_list[pos] = src;
    }
}

// ---------------- weight convert -> row-major bf16 hi/lo [768][672] -----------
__global__ void conv_weights(const float* __restrict__ wl, const float* __restrict__ wr) {
    int idx = blockIdx.x * blockDim.x + threadIdx.x;   // over 768 * 168 quads
    if (idx >= NPAD * (LKB / 4)) return;
    int nrow = idx / (LKB / 4);
    int k0   = (idx % (LKB / 4)) * 4;
    size_t off = (size_t)nrow * LKB + k0;
    uint16_t lh[4], ll[4], rh[4], rl[4];
#pragma unroll
    for (int e = 0; e < 4; e++) {
        int k = k0 + e;
        float a = (nrow < F_DIM && k < F_DIM) ? wl[(size_t)nrow * F_DIM + k] : 0.f;
        float b = (nrow < F_DIM && k < F_DIM) ? wr[(size_t)nrow * F_DIM + k] : 0.f;
        bsplit(a, lh[e], ll[e]);
        bsplit(b, rh[e], rl[e]);
    }
    *(uint2*)(g_wlh + off) = pack4(lh[0], lh[1], lh[2], lh[3]);
    *(uint2*)(g_wll + off) = pack4(ll[0], ll[1], ll[2], ll[3]);
    *(uint2*)(g_wrh + off) = pack4(rh[0], rh[1], rh[2], rh[3]);
    *(uint2*)(g_wrl + off) = pack4(rl[0], rl[1], rl[2], rl[3]);
}

// ---------------- grouped Conv1d -> bufA (fp32) + hh0/hl0 (bf16) --------------
#define XS_STRIDE 660
#define CONV_SMEM ((16 * XS_STRIDE + 64 * 80) * 4)
__global__ void conv1d_grouped(const float* __restrict__ x,
                               const float* __restrict__ w,
                               const float* __restrict__ b) {
    float* smem = (float*)dyn_smem;
    float* xs = smem;
    float* ws = smem + 16 * XS_STRIDE;
    int n = blockIdx.x, g = blockIdx.y;
    int tid = threadIdx.x;

    const float* xbase = x + ((size_t)n * C_IN + (size_t)g * 16) * T_IN;
    for (int i = tid; i < 16 * T_IN; i += blockDim.x) {
        int ic = i / T_IN, t = i % T_IN;
        xs[ic * XS_STRIDE + t] = xbase[i];
    }
    for (int i = tid; i < 64 * 80; i += blockDim.x)
        ws[i] = w[(size_t)g * 64 * 80 + i];
    __syncthreads();

    for (int task = tid; task < 64 * 164; task += blockDim.x) {
        int oc = task / 164;
        int t0 = (task % 164) * 4;
        float bias = b[g * 64 + oc];
        float a0 = bias, a1 = bias, a2 = bias, a3 = bias;
        const float* wrow = &ws[oc * 80];
#pragma unroll
        for (int i = 0; i < 16; i++) {
            float4 x0 = *(const float4*)&xs[i * XS_STRIDE + t0];
            float4 x1 = *(const float4*)&xs[i * XS_STRIDE + t0 + 4];
            float xv[8] = {x0.x, x0.y, x0.z, x0.w, x1.x, x1.y, x1.z, x1.w};
#pragma unroll
            for (int k = 0; k < 5; k++) {
                float wv = wrow[i * 5 + k];
                a0 = fmaf(xv[0 + k], wv, a0);
                a1 = fmaf(xv[1 + k], wv, a1);
                a2 = fmaf(xv[2 + k], wv, a2);
                a3 = fmaf(xv[3 + k], wv, a3);
            }
        }
        float z0 = (t0 + 0 < F_DIM) ? a0 : 0.f;
        float z1 = (t0 + 1 < F_DIM) ? a1 : 0.f;
        float z2 = (t0 + 2 < F_DIM) ? a2 : 0.f;
        float z3 = (t0 + 3 < F_DIM) ? a3 : 0.f;
        int row = n * C_OUT + g * 64 + oc;
        float* out = &g_bufA[(size_t)row * LDF + t0];
        out[0] = z0; out[1] = z1; out[2] = z2; out[3] = z3;
        uint16_t h[4], l[4];
        bsplit(z0, h[0], l[0]); bsplit(z1, h[1], l[1]);
        bsplit(z2, h[2], l[2]); bsplit(z3, h[3], l[3]);
        size_t off = (size_t)row * LKB + t0;
        *(uint2*)(g_hh0 + off) = pack4(h[0], h[1], h[2], h[3]);
        *(uint2*)(g_hl0 + off) = pack4(l[0], l[1], l[2], l[3]);
    }
    // zero the bf16 K-pad tail (cols 656..671) for this block's 64 rows
    for (int i = tid; i < 64 * 4; i += blockDim.x) {
        int oc = i / 4;
        int c0 = 656 + (i % 4) * 4;
        int row = n * C_OUT + g * 64 + oc;
        size_t off = (size_t)row * LKB + c0;
        *(uint2*)(g_hh0 + off) = make_uint2(0u, 0u);
        *(uint2*)(g_hl0 + off) = make_uint2(0u, 0u);
    }
}

// ---------------- SAGE max-aggregation -> aggh/aggl (bf16 row-major) ----------
__global__ void sage_agg(int src) {
    const float* h = src ? g_bufB : g_bufA;
    int row = blockIdx.x;          // n*256 + c
    int n = row >> 8;
    int c = row & 255;
    int beg = g_offs[n], end = g_offs[n + 1];
    size_t obase = (size_t)row * LKB;
    for (int v = threadIdx.x; v < LKB / 4; v += blockDim.x) {
        int f0 = v * 4;
        float4 m = make_float4(0.f, 0.f, 0.f, 0.f);
        if (f0 < LDF && end > beg) {
            m = make_float4(-3.4e38f, -3.4e38f, -3.4e38f, -3.4e38f);
            for (int e = beg; e < end; e++) {
                int s = g_list[e];
                float4 t = *(const float4*)(h + ((size_t)s * C_OUT + c) * LDF + f0);
                m.x = fmaxf(m.x, t.x); m.y = fmaxf(m.y, t.y);
                m.z = fmaxf(m.z, t.z); m.w = fmaxf(m.w, t.w);
            }
        }
        uint16_t hh[4], ll[4];
        bsplit(m.x, hh[0], ll[0]); bsplit(m.y, hh[1], ll[1]);
        bsplit(m.z, hh[2], ll[2]); bsplit(m.w, hh[3], ll[3]);
        *(uint2*)(g_aggh + obase + f0) = pack4(hh[0], hh[1], hh[2], hh[3]);
        *(uint2*)(g_aggl + obase + f0) = pack4(ll[0], ll[1], ll[2], ll[3]);
    }
}

// ---------------- WMMA fused SAGE GEMM ----------------------------------------
// C[128x128] = agg@Wl^T + h@Wr^T (3-term bf16 split), bias added in epilogue.
// smem rows padded to SROW=56 bf16 (112B) -> conflict-free ldmatrix.
__device__ __forceinline__ void stage_copy(uint32_t sbase, int tid,
                                           const __nv_bfloat16* pAh, const __nv_bfloat16* pAl,
                                           const __nv_bfloat16* pBh, const __nv_bfloat16* pBl) {
#pragma unroll
    for (int half = 0; half < 2; half++) {
        int c = tid + half * 256;       // 0..511
        int row = c >> 2;               // 0..127
        int col = (c & 3) << 3;         // 0,8,16,24
        uint32_t so = (uint32_t)row * (SROW * 2) + col * 2;
        size_t go = (size_t)row * LKB + col;
        cpa16(sbase +             so, pAh + go);
        cpa16(sbase + MAT_B     + so, pAl + go);
        cpa16(sbase + MAT_B * 2 + so, pBh + go);
        cpa16(sbase + MAT_B * 3 + so, pBl + go);
    }
    CP_COMMIT();
}

__global__ void __launch_bounds__(256, 2) sage_gemm(int src, int writeB,
                                                    const float* __restrict__ bias) {
    __shared__ float sbias[128];
    const int tid = threadIdx.x;
    const int wid = tid >> 5;
    const int m0 = blockIdx.x * 128;
    const int n0 = blockIdx.y * 128;

    const __nv_bfloat16* AhArr[2] = { g_aggh, src ? g_hh1 : g_hh0 };
    const __nv_bfloat16* AlArr[2] = { g_aggl, src ? g_hl1 : g_hl0 };
    const __nv_bfloat16* BhArr[2] = { g_wlh, g_wrh };
    const __nv_bfloat16* BlArr[2] = { g_wll, g_wrl };
    float*          Out  = src ? g_bufA : g_bufB;
    __nv_bfloat16*  OutH = src ? g_hh0 : g_hh1;
    __nv_bfloat16*  OutL = src ? g_hl0 : g_hl1;

    if (tid < 128) {
        int cg = n0 + tid;
        sbias[tid] = (cg < F_DIM) ? bias[cg] : 0.f;
    }

    const uint32_t smem_base = smem_u32(dyn_smem);

    // prologue: stages 0,1 (both phase 0 since KT_PHASE=21 > 1)
#pragma unroll
    for (int p = 0; p < 2; p++) {
        int k0 = p * BK;
        stage_copy(smem_base + p * STAGE_B, tid,
                   AhArr[0] + (size_t)m0 * LKB + k0,
                   AlArr[0] + (size_t)m0 * LKB + k0,
                   BhArr[0] + (size_t)n0 * LKB + k0,
                   BlArr[0] + (size_t)n0 * LKB + k0);
    }

    const int wm = (wid & 3) * 32;      // warp m offset within tile
    const int wn = (wid >> 2) * 64;     // warp n offset within tile

    wmma::fragment<wmma::accumulator, 16, 16, 16, float> acc[2][4];
#pragma unroll
    for (int i = 0; i < 2; i++)
#pragma unroll
        for (int j = 0; j < 4; j++) wmma::fill_fragment(acc[i][j], 0.f);

    for (int kt = 0; kt < KT_TOTAL; kt++) {
        CP_WAIT1();
        __syncthreads();
        const __nv_bfloat16* sA = (const __nv_bfloat16*)(dyn_smem + (kt & 1) * STAGE_B);
        const __nv_bfloat16* sBh = sA + OFF_BH;
#pragma unroll
        for (int ks = 0; ks < 2; ks++) {
            wmma::fragment<wmma::matrix_a, 16, 16, 16, __nv_bfloat16, wmma::row_major> ah[2], al[2];
            wmma::fragment<wmma::matrix_b, 16, 16, 16, __nv_bfloat16, wmma::col_major> bh[4], bl[4];
#pragma unroll
            for (int i = 0; i < 2; i++) {
                const __nv_bfloat16* pa = sA + (wm + i * 16) * SROW + ks * 16;
                wmma::load_matrix_sync(ah[i], pa, SROW);
                wmma::load_matrix_sync(al[i], pa + OFF_AL, SROW);
            }
#pragma unroll
            for (int j = 0; j < 4; j++) {
                const __nv_bfloat16* pb = sBh + (wn + j * 16) * SROW + ks * 16;
                wmma::load_matrix_sync(bh[j], pb, SROW);
                wmma::load_matrix_sync(bl[j], pb + OFF_AL, SROW);
            }
#pragma unroll
            for (int i = 0; i < 2; i++)
#pragma unroll
                for (int j = 0; j < 4; j++) {
                    wmma::mma_sync(acc[i][j], ah[i], bh[j], acc[i][j]);
                    wmma::mma_sync(acc[i][j], al[i], bh[j], acc[i][j]);
                    wmma::mma_sync(acc[i][j], ah[i], bl[j], acc[i][j]);
                }
        }
        __syncthreads();           // all warps done reading stage kt&1
        int nk = kt + 2;
        if (nk < KT_TOTAL) {
            int ph = (nk >= KT_PHASE) ? 1 : 0;
            int k0 = (nk - ph * KT_PHASE) * BK;
            stage_copy(smem_base + (kt & 1) * STAGE_B, tid,
                       AhArr[ph] + (size_t)m0 * LKB + k0,
                       AlArr[ph] + (size_t)m0 * LKB + k0,
                       BhArr[ph] + (size_t)n0 * LKB + k0,
                       BlArr[ph] + (size_t)n0 * LKB + k0);
        } else {
            CP_COMMIT();           // keep group counting consistent for CP_WAIT1
        }
    }

    // epilogue: stage accumulators through smem (reuse pipeline smem)
    __syncthreads();
    float* Cs = (float*)dyn_smem;       // [128][132]
#pragma unroll
    for (int i = 0; i < 2; i++)
#pragma unroll
        for (int j = 0; j < 4; j++)
            wmma::store_matrix_sync(&Cs[(wm + i * 16) * 132 + wn + j * 16], acc[i][j],
                                    132, wmma::mem_row_major);
    __syncthreads();

#pragma unroll
    for (int t = 0; t < 16; t++) {
        int q = tid + t * 256;          // 0..4095
        int row = q >> 5;
        int col = (q & 31) * 4;
        float v0 = Cs[row * 132 + col + 0] + sbias[col + 0];
        float v1 = Cs[row * 132 + col + 1] + sbias[col + 1];
        float v2 = Cs[row * 132 + col + 2] + sbias[col + 2];
        float v3 = Cs[row * 132 + col + 3] + sbias[col + 3];
        int cg = n0 + col;
        int m = m0 + row;
        if (cg < LDF) {
            *(float4*)(Out + (size_t)m * LDF + cg) = make_float4(v0, v1, v2, v3);
        }
        if (writeB && cg < LKB) {
            uint16_t h[4], l[4];
            bsplit(v0, h[0], l[0]); bsplit(v1, h[1], l[1]);
            bsplit(v2, h[2], l[2]); bsplit(v3, h[3], l[3]);
            size_t off = (size_t)m * LKB + cg;
            *(uint2*)(OutH + off) = pack4(h[0], h[1], h[2], h[3]);
            *(uint2*)(OutL + off) = pack4(l[0], l[1], l[2], l[3]);
        }
    }
}

// ---------------- mean pool -> g_mean ------------------------------------------
__global__ void mean_pool(int src) {
    const float* h = src ? g_bufB : g_bufA;
    int idx = blockIdx.x * blockDim.x + threadIdx.x;
    if (idx >= C_OUT * LDF) return;
    int c = idx / LDF, f = idx % LDF;
    float s = 0.f;
    for (int n = 0; n < N_NODES; n++)
        s += h[((size_t)n * C_OUT + c) * LDF + f];
    g_mean[idx] = s * (1.f / N_NODES);
}

__device__ __forceinline__ float gelu_exact(float x) {
    return 0.5f * x * (1.f + erff(x * 0.70710678118654752f));
}

// ---------------- fc1 + gelu ----------------------------------------------------
__global__ void fc1_kernel(const float* __restrict__ w, const float* __restrict__ b) {
    __shared__ float row[F_DIM];
    int c = blockIdx.x;
    int tid = threadIdx.x;
    for (int f = tid; f < F_DIM; f += blockDim.x) row[f] = g_mean[c * LDF + f];
    __syncthreads();
    int warp = tid >> 5, lane = tid & 31;
    for (int g = warp; g < 128; g += blockDim.x / 32) {
        const float* wr = w + (size_t)g * F_DIM;
        float acc = 0.f;
        for (int f = lane; f < F_DIM; f += 32) acc = fmaf(row[f], wr[f], acc);
#pragma unroll
        for (int o = 16; o; o >>= 1) acc += __shfl_xor_sync(0xffffffffu, acc, o);
        if (lane == 0) g_fc1[c * 128 + g] = gelu_exact(acc + b[g]);
    }
}

// ---------------- fc2 + gelu + fc3 + softmax ------------------------------------
__global__ void head_kernel(const float* __restrict__ f2w, const float* __restrict__ f2b,
                            const float* __restrict__ f3w, const float* __restrict__ f3b,
                            float* __restrict__ out) {
    __shared__ float r1[128];
    __shared__ float r2[32];
    __shared__ float r3[4];
    int c = blockIdx.x;
    int tid = threadIdx.x;
    for (int i = tid; i < 128; i += 32) r1[i] = g_fc1[c * 128 + i];
    __syncthreads();
    {
        float acc = f2b[tid];
        const float* wr = f2w + (size_t)tid * 128;
        for (int f = 0; f < 128; f++) acc = fmaf(r1[f], wr[f], acc);
        r2[tid] = gelu_exact(acc);
    }
    __syncthreads();
    if (tid < 4) {
        float a = f3b[tid];
        const float* wr = f3w + (size_t)tid * 32;
        for (int f = 0; f < 32; f++) a = fmaf(r2[f], wr[f], a);
        r3[tid] = a;
    }
    __syncthreads();
    if (tid == 0) {
        float mx = fmaxf(fmaxf(r3[0], r3[1]), fmaxf(r3[2], r3[3]));
        float e0 = expf(r3[0] - mx), e1 = expf(r3[1] - mx);
        float e2 = expf(r3[2] - mx), e3 = expf(r3[3] - mx);
        float inv = 1.f / (e0 + e1 + e2 + e3);
        out[c * 4 + 0] = e0 * inv;
        out[c * 4 + 1] = e1 * inv;
        out[c * 4 + 2] = e2 * inv;
        out[c * 4 + 3] = e3 * inv;
    }
}

// ---------------- launch --------------------------------------------------------
extern "C" void kernel_launch(void* const* d_in, const int* in_sizes, int n_in,
                              void* d_out, int out_size) {
    const float* x      = (const float*)d_in[0];
    const int*   ei     = (const int*)d_in[1];
    const float* conv_w = (const float*)d_in[2];
    const float* conv_b = (const float*)d_in[3];
    const float* wl     = (const float*)d_in[4];
    const float* wr     = (const float*)d_in[5];
    const float* sb     = (const float*)d_in[6];
    const float* f1w    = (const float*)d_in[7];
    const float* f1b    = (const float*)d_in[8];
    const float* f2w    = (const float*)d_in[9];
    const float* f2b    = (const float*)d_in[10];
    const float* f3w    = (const float*)d_in[11];
    const float* f3b    = (const float*)d_in[12];
    float* out = (float*)d_out;

    cudaFuncSetAttribute(conv1d_grouped, cudaFuncAttributeMaxDynamicSharedMemorySize, CONV_SMEM);
    cudaFuncSetAttribute(sage_gemm,      cudaFuncAttributeMaxDynamicSharedMemorySize, GEMM_SMEM);

    build_csr<<<1, 128>>>(ei);
    conv_weights<<<(NPAD * (LKB / 4) + 255) / 256, 256>>>(wl, wr);
    conv1d_grouped<<<dim3(N_NODES, 4), 256, CONV_SMEM>>>(x, conv_w, conv_b);

    // 3 SAGE layers. l0: A->B (h: hh0 -> hh1), l1: B->A (hh1 -> hh0), l2: A->B
    for (int l = 0; l < 3; l++) {
        int src = l & 1;
        sage_agg<<<M_ROWS, 128>>>(src);
        sage_gemm<<<dim3(M_TILES, N_TILES), 256, GEMM_SMEM>>>(src, l < 2 ? 1 : 0, sb);
    }

    mean_pool<<<(C_OUT * LDF + 255) / 256, 256>>>(1);
    fc1_kernel<<<256, 128>>>(f1w, f1b);
    head_kernel<<<256, 32>>>(f2w, f2b, f3w, f3b, out);
}